// round 13
// baseline (speedup 1.0000x reference)
#include <cuda_runtime.h>
#include <cuda_bf16.h>
#include <cstdint>

// Fixed shapes: [16, 4096, 2] fp32 both inputs
#define NOBJ 16
#define P    4096
#define BQ   128      // queries per CTA
#define BR   512      // refs staged per chunk
#define NCHUNK (P/BR)
#define NQUAD (BR/4)  // ref-quads per chunk
#define EPSF 1e-12f

// Scratch (allocation-free)
static __device__ float g_sum1[NOBJ * 32];
static __device__ float g_sum2[NOBJ * 32];
static __device__ float g_cost[NOBJ];

// ---- packed fp32x2 helpers (FFMA2 is PTX-only; ptxas won't auto-fuse) ----
__device__ __forceinline__ unsigned long long pack2(float lo, float hi) {
    unsigned long long r;
    asm("mov.b64 %0, {%1, %2};" : "=l"(r) : "f"(lo), "f"(hi));
    return r;
}
__device__ __forceinline__ void unpack2(unsigned long long v, float& lo, float& hi) {
    asm("mov.b64 {%0, %1}, %2;" : "=f"(lo), "=f"(hi) : "l"(v));
}
__device__ __forceinline__ unsigned long long fma2(unsigned long long a,
                                                   unsigned long long b,
                                                   unsigned long long c) {
    unsigned long long d;
    asm("fma.rn.f32x2 %0, %1, %2, %3;" : "=l"(d) : "l"(a), "l"(b), "l"(c));
    return d;
}

// ---------------------------------------------------------------------------
// Both chamfer directions in ONE launch: dir = blockIdx.z.
// R13 scheme: refs stored PACKED (no (v,v) duplication); query coefficients
// duplicated into registers instead. Per jj each thread loads a ref-QUAD via
// 3x LDS.128 (sX4/sY4/sY24) and computes 8 queries x 4 refs = 32 pairs:
//   per query: 4 FFMA2 + 4 FMNMX  ->  2.09 issue-slots/pair,
//   smem traffic 0.75 B/pair (was 1.5).
// No launch_bounds clamp (R4/R8: clamping spills). BR=512 halves barriers.
// ---------------------------------------------------------------------------
__global__ void k_pass(const float* __restrict__ pt1,
                       const float* __restrict__ pt2) {
    const int n = blockIdx.y, tile = blockIdx.x, tid = threadIdx.x;
    const int dir = blockIdx.z;
    const int tx = tid & 15, ty = tid >> 4;

    const float* q = dir ? pt2 : pt1;
    const float* r = dir ? pt1 : pt2;

    __shared__ float sXf[BR], sYf[BR], sY2f[BR];
    __shared__ float2 sQ[BQ];
    __shared__ float  sRed[16];

    const float2* qp = reinterpret_cast<const float2*>(q) + n * P + tile * BQ;
    const float2* rp = reinterpret_cast<const float2*>(r) + n * P;

    if (tid < BQ) sQ[tid] = qp[tid];
    float2 y0 = rp[tid];                 // prefetch chunk 0 (512 refs: 2/thread)
    float2 y1 = rp[tid + 256];
    __syncthreads();

    // per-query coefficients, duplicated into packed u64 (registers: free dup)
    unsigned long long m2a[8], m2b[8];
    float rmin[8];
    #pragma unroll
    for (int i = 0; i < 8; i++) {
        float2 x = sQ[ty * 8 + i];
        m2a[i] = pack2(-2.0f * x.x, -2.0f * x.x);
        m2b[i] = pack2(-2.0f * x.y, -2.0f * x.y);
        rmin[i] = 3.402823466e38f;
    }

    const float4* sX4  = reinterpret_cast<const float4*>(sXf);
    const float4* sY4  = reinterpret_cast<const float4*>(sYf);
    const float4* sY24 = reinterpret_cast<const float4*>(sY2f);

    for (int jc = 0; jc < NCHUNK; jc++) {
        __syncthreads();                 // consumers done with previous chunk
        sXf[tid]        = y0.x;
        sYf[tid]        = y0.y;
        sY2f[tid]       = fmaf(y0.x, y0.x, y0.y * y0.y);
        sXf[tid + 256]  = y1.x;
        sYf[tid + 256]  = y1.y;
        sY2f[tid + 256] = fmaf(y1.x, y1.x, y1.y * y1.y);
        if (jc + 1 < NCHUNK) {           // overlap next-chunk LDG with compute
            y0 = rp[(jc + 1) * BR + tid];
            y1 = rp[(jc + 1) * BR + tid + 256];
        }
        __syncthreads();

        #pragma unroll 2
        for (int jj = 0; jj < NQUAD / 16; jj++) {
            const int c = jj * 16 + tx;  // ref-quad index; conflict-free
            float4 vx = sX4[c];
            float4 vy = sY4[c];
            float4 v2 = sY24[c];
            unsigned long long yx01, yx23, yy01, yy23, y201, y223;
            asm("mov.b64 %0, {%2, %3}; mov.b64 %1, {%4, %5};"
                : "=l"(yx01), "=l"(yx23)
                : "f"(vx.x), "f"(vx.y), "f"(vx.z), "f"(vx.w));
            asm("mov.b64 %0, {%2, %3}; mov.b64 %1, {%4, %5};"
                : "=l"(yy01), "=l"(yy23)
                : "f"(vy.x), "f"(vy.y), "f"(vy.z), "f"(vy.w));
            asm("mov.b64 %0, {%2, %3}; mov.b64 %1, {%4, %5};"
                : "=l"(y201), "=l"(y223)
                : "f"(v2.x), "f"(v2.y), "f"(v2.z), "f"(v2.w));
            #pragma unroll
            for (int i = 0; i < 8; i++) {
                unsigned long long u01 = fma2(m2a[i], yx01, y201);
                u01 = fma2(m2b[i], yy01, u01);
                unsigned long long u23 = fma2(m2a[i], yx23, y223);
                u23 = fma2(m2b[i], yy23, u23);
                float u0, u1, u2, u3;
                unpack2(u01, u0, u1);
                unpack2(u23, u2, u3);
                rmin[i] = fminf(rmin[i], fminf(u0, u1));
                rmin[i] = fminf(rmin[i], fminf(u2, u3));
            }
        }
    }

    // epilogue: min across the 16 tx lanes of each ty group; x2 recomputed here
    float rs = 0.0f;
    #pragma unroll
    for (int i = 0; i < 8; i++) {
        float v = rmin[i];
        #pragma unroll
        for (int off = 8; off >= 1; off >>= 1)
            v = fminf(v, __shfl_xor_sync(0xffffffffu, v, off, 16));
        if (tx == 0) {
            float2 x = sQ[ty * 8 + i];
            float x2 = fmaf(x.x, x.x, x.y * x.y);
            rs += sqrtf(fmaxf(x2 + v, EPSF));
        }
    }
    if (tx == 0) sRed[ty] = rs;
    __syncthreads();
    if (tid == 0) {
        float s = 0.0f;
        #pragma unroll
        for (int t = 0; t < 16; t++) s += sRed[t];
        (dir ? g_sum2 : g_sum1)[n * 32 + tile] = s;
    }
}

// ---------------------------------------------------------------------------
// Finalize stage 1: one block per object (mask + per-object masked cost).
// ---------------------------------------------------------------------------
__global__ void k_final1(const float* __restrict__ pt2, float* __restrict__ unused) {
    __shared__ float sred[256];
    const int n = blockIdx.x, tid = threadIdx.x;

    float s = 0.0f;
    const float4* p = reinterpret_cast<const float4*>(pt2 + n * P * 2);
    #pragma unroll
    for (int i = 0; i < (P * 2 / 4) / 256; i++) {   // 8 independent loads
        float4 v = p[i * 256 + tid];
        s += (v.x + v.y) + (v.z + v.w);
    }
    sred[tid] = s;
    __syncthreads();
    #pragma unroll
    for (int st = 128; st > 0; st >>= 1) {
        if (tid < st) sred[tid] += sred[tid + st];
        __syncthreads();
    }
    if (tid == 0) {
        float mask = sred[0];
        float s1 = 0.0f, s2 = 0.0f;
        #pragma unroll
        for (int t = 0; t < 32; t++) {
            s1 += g_sum1[n * 32 + t];
            s2 += g_sum2[n * 32 + t];
        }
        g_cost[n] = (mask >= 0.0f) ? 0.5f * (s1 + s2) * (1.0f / P) : 0.0f;
    }
}

// Finalize stage 2: sum 16 per-object costs.
__global__ void k_final2(float* __restrict__ out) {
    if (threadIdx.x == 0) {
        float s = 0.0f;
        #pragma unroll
        for (int t = 0; t < NOBJ; t++) s += g_cost[t];
        out[0] = s * (1.0f / NOBJ);
    }
}

// ---------------------------------------------------------------------------
extern "C" void kernel_launch(void* const* d_in, const int* in_sizes, int n_in,
                              void* d_out, int out_size) {
    const float* pt1 = reinterpret_cast<const float*>(d_in[0]);
    const float* pt2 = reinterpret_cast<const float*>(d_in[1]);
    float* out = reinterpret_cast<float*>(d_out);
    (void)in_sizes; (void)n_in; (void)out_size;

    dim3 grid(P / BQ, NOBJ, 2);   // (32, 16, 2) — both directions, one launch
    k_pass<<<grid, 256>>>(pt1, pt2);
    k_final1<<<NOBJ, 256>>>(pt2, out);
    k_final2<<<1, 32>>>(out);
}

// round 16
// speedup vs baseline: 1.4641x; 1.4641x over previous
#include <cuda_runtime.h>
#include <cuda_bf16.h>
#include <cstdint>

// Fixed shapes: [16, 4096, 2] fp32 both inputs
#define NOBJ 16
#define P    4096
#define BQ   128      // queries per CTA
#define BR   256      // refs staged per chunk
#define NCHUNK (P/BR)
#define NT   128      // threads per CTA (R15: was 256 -> single-wave grid)
#define EPSF 1e-12f

// Scratch (allocation-free)
static __device__ float g_sum1[NOBJ * 32];
static __device__ float g_sum2[NOBJ * 32];
static __device__ float g_cost[NOBJ];

// ---- packed fp32x2 helpers (FFMA2 is PTX-only; no packed f32 min exists) ----
__device__ __forceinline__ unsigned long long pack2(float lo, float hi) {
    unsigned long long r;
    asm("mov.b64 %0, {%1, %2};" : "=l"(r) : "f"(lo), "f"(hi));
    return r;
}
__device__ __forceinline__ void unpack2(unsigned long long v, float& lo, float& hi) {
    asm("mov.b64 {%0, %1}, %2;" : "=f"(lo), "=f"(hi) : "l"(v));
}
__device__ __forceinline__ unsigned long long fma2(unsigned long long a,
                                                   unsigned long long b,
                                                   unsigned long long c) {
    unsigned long long d;
    asm("fma.rn.f32x2 %0, %1, %2, %3;" : "=l"(d) : "l"(a), "l"(b), "l"(c));
    return d;
}

// ---------------------------------------------------------------------------
// Both chamfer directions in ONE launch: dir = blockIdx.z.
// R15 = R12 inner loop (best known: 2 LDS + 8 FFMA2 + 8 FMNMX per 8 pairs)
// with 128-thread CTAs: tx = tid&7 (8 ref lanes), ty = tid>>3 (16 query
// groups x 8 queries = 128 queries/CTA). Same work per CTA, but per-SM CTA
// limit >= 7 => all 1024 CTAs resident in ONE wave (was 1.73 waves @ 256thr).
// No launch_bounds clamp (R4/R8: clamping spills). Unroll 4 (R11).
// ---------------------------------------------------------------------------
__global__ void k_pass(const float* __restrict__ pt1,
                       const float* __restrict__ pt2) {
    const int n = blockIdx.y, tile = blockIdx.x, tid = threadIdx.x;
    const int dir = blockIdx.z;
    const int tx = tid & 7, ty = tid >> 3;

    const float* q = dir ? pt2 : pt1;
    const float* r = dir ? pt1 : pt2;

    __shared__ float4 sAB[BR];
    __shared__ unsigned long long sC[BR];
    __shared__ float2 sQ[BQ];
    __shared__ float  sRed[16];

    const float2* qp = reinterpret_cast<const float2*>(q) + n * P + tile * BQ;
    const float2* rp = reinterpret_cast<const float2*>(r) + n * P;

    sQ[tid] = qp[tid];                   // 128 threads load 128 queries
    float2 y0 = rp[tid];                 // prefetch chunk 0 (2 refs/thread)
    float2 y1 = rp[tid + NT];
    __syncthreads();

    unsigned long long m2a[4], m2b[4];
    float rmin[8];
    #pragma unroll
    for (int p = 0; p < 4; p++) {
        float2 xa = sQ[ty * 8 + 2 * p];
        float2 xb = sQ[ty * 8 + 2 * p + 1];
        m2a[p] = pack2(-2.0f * xa.x, -2.0f * xb.x);
        m2b[p] = pack2(-2.0f * xa.y, -2.0f * xb.y);
    }
    #pragma unroll
    for (int i = 0; i < 8; i++) rmin[i] = 3.402823466e38f;

    for (int jc = 0; jc < NCHUNK; jc++) {
        __syncthreads();                 // consumers done with previous chunk
        sAB[tid] = make_float4(y0.x, y0.x, y0.y, y0.y);
        sAB[tid + NT] = make_float4(y1.x, y1.x, y1.y, y1.y);
        float yy0 = fmaf(y0.x, y0.x, y0.y * y0.y);
        float yy1 = fmaf(y1.x, y1.x, y1.y * y1.y);
        sC[tid] = pack2(yy0, yy0);
        sC[tid + NT] = pack2(yy1, yy1);
        if (jc + 1 < NCHUNK) {           // overlap next-chunk LDG with compute
            y0 = rp[(jc + 1) * BR + tid];
            y1 = rp[(jc + 1) * BR + tid + NT];
        }
        __syncthreads();

        #pragma unroll 4
        for (int jj = 0; jj < BR / 8; jj++) {
            const int c = jj * 8 + tx;   // 8 distinct + 4-way broadcast: N=1
            float4 v = sAB[c];
            unsigned long long ya, yb;
            asm("mov.b64 %0, {%2, %3}; mov.b64 %1, {%4, %5};"
                : "=l"(ya), "=l"(yb)
                : "f"(v.x), "f"(v.y), "f"(v.z), "f"(v.w));
            const unsigned long long yc = sC[c];
            #pragma unroll
            for (int p = 0; p < 4; p++) {
                unsigned long long u2 = fma2(m2a[p], ya, yc);
                u2 = fma2(m2b[p], yb, u2);
                float u0, u1;
                unpack2(u2, u0, u1);
                rmin[2 * p]     = fminf(rmin[2 * p], u0);
                rmin[2 * p + 1] = fminf(rmin[2 * p + 1], u1);
            }
        }
    }

    // epilogue: min across the 8 tx lanes of each ty group (width=8)
    float rs = 0.0f;
    #pragma unroll
    for (int i = 0; i < 8; i++) {
        float v = rmin[i];
        #pragma unroll
        for (int off = 4; off >= 1; off >>= 1)
            v = fminf(v, __shfl_xor_sync(0xffffffffu, v, off, 8));
        if (tx == 0) {
            float2 x = sQ[ty * 8 + i];
            float x2 = fmaf(x.x, x.x, x.y * x.y);
            rs += sqrtf(fmaxf(x2 + v, EPSF));
        }
    }
    if (tx == 0) sRed[ty] = rs;
    __syncthreads();
    if (tid == 0) {
        float s = 0.0f;
        #pragma unroll
        for (int t = 0; t < 16; t++) s += sRed[t];
        (dir ? g_sum2 : g_sum1)[n * 32 + tile] = s;
    }
}

// ---------------------------------------------------------------------------
// Finalize stage 1: one block per object (mask + per-object masked cost).
// ---------------------------------------------------------------------------
__global__ void k_final1(const float* __restrict__ pt2, float* __restrict__ unused) {
    __shared__ float sred[256];
    const int n = blockIdx.x, tid = threadIdx.x;

    float s = 0.0f;
    const float4* p = reinterpret_cast<const float4*>(pt2 + n * P * 2);
    #pragma unroll
    for (int i = 0; i < (P * 2 / 4) / 256; i++) {   // 8 independent loads
        float4 v = p[i * 256 + tid];
        s += (v.x + v.y) + (v.z + v.w);
    }
    sred[tid] = s;
    __syncthreads();
    #pragma unroll
    for (int st = 128; st > 0; st >>= 1) {
        if (tid < st) sred[tid] += sred[tid + st];
        __syncthreads();
    }
    if (tid == 0) {
        float mask = sred[0];
        float s1 = 0.0f, s2 = 0.0f;
        #pragma unroll
        for (int t = 0; t < 32; t++) {
            s1 += g_sum1[n * 32 + t];
            s2 += g_sum2[n * 32 + t];
        }
        g_cost[n] = (mask >= 0.0f) ? 0.5f * (s1 + s2) * (1.0f / P) : 0.0f;
    }
}

// Finalize stage 2: sum 16 per-object costs.
__global__ void k_final2(float* __restrict__ out) {
    if (threadIdx.x == 0) {
        float s = 0.0f;
        #pragma unroll
        for (int t = 0; t < NOBJ; t++) s += g_cost[t];
        out[0] = s * (1.0f / NOBJ);
    }
}

// ---------------------------------------------------------------------------
extern "C" void kernel_launch(void* const* d_in, const int* in_sizes, int n_in,
                              void* d_out, int out_size) {
    const float* pt1 = reinterpret_cast<const float*>(d_in[0]);
    const float* pt2 = reinterpret_cast<const float*>(d_in[1]);
    float* out = reinterpret_cast<float*>(d_out);
    (void)in_sizes; (void)n_in; (void)out_size;

    dim3 grid(P / BQ, NOBJ, 2);   // (32, 16, 2) — both directions, one launch
    k_pass<<<grid, NT>>>(pt1, pt2);
    k_final1<<<NOBJ, 256>>>(pt2, out);
    k_final2<<<1, 32>>>(out);
}

// round 17
// speedup vs baseline: 1.5229x; 1.0402x over previous
#include <cuda_runtime.h>
#include <cuda_bf16.h>
#include <cstdint>
#include <cfloat>

// Fixed shapes: [16, 4096, 2] fp32 both inputs
#define NOBJ 16
#define P     4096
#define EPSF  1e-12f

// Grid for exact NN search
#define G       64
#define NBINS   (G*G)
#define GLO     (-5.5f)
#define GHI     (5.5f)
#define CELL    (11.0f / 64.0f)
#define INVCELL (64.0f / 11.0f)

// Scratch (allocation-free, __device__ globals)
static __device__ int    g_cnt   [NOBJ * 2 * NBINS];
static __device__ int    g_start [NOBJ * 2 * (NBINS + 1)];
static __device__ int    g_cursor[NOBJ * 2 * NBINS];
static __device__ int    g_ovfcnt[NOBJ * 2];
static __device__ float2 g_spts  [NOBJ * 2 * P];
static __device__ float2 g_ovf   [NOBJ * 2 * P];
static __device__ float  g_sum   [2 * NOBJ * 16];   // [qs][n][blk]
static __device__ float  g_cost  [NOBJ];

__device__ __forceinline__ int bin_coord(float v) {
    int b = (int)floorf((v - GLO) * INVCELL);
    return min(max(b, 0), G - 1);
}
__device__ __forceinline__ bool in_box(float2 p) {
    return p.x >= GLO && p.x <= GHI && p.y >= GLO && p.y <= GHI;
}

// ---------------------------------------------------------------------------
// 1) zero counters
// ---------------------------------------------------------------------------
__global__ void k_zero() {
    int i = blockIdx.x * 256 + threadIdx.x;
    if (i < NOBJ * 2 * NBINS) g_cnt[i] = 0;
    if (i < NOBJ * 2) g_ovfcnt[i] = 0;
}

// ---------------------------------------------------------------------------
// 2) count points per bin. grid (P/256, NOBJ, 2)
// ---------------------------------------------------------------------------
__global__ void k_count(const float* __restrict__ pt1, const float* __restrict__ pt2) {
    const int i = blockIdx.x * 256 + threadIdx.x;
    const int n = blockIdx.y, s = blockIdx.z;
    const int slice = n * 2 + s;
    float2 p = reinterpret_cast<const float2*>(s ? pt2 : pt1)[n * P + i];
    if (in_box(p)) {
        int b = bin_coord(p.y) * G + bin_coord(p.x);
        atomicAdd(&g_cnt[slice * NBINS + b], 1);
    }
}

// ---------------------------------------------------------------------------
// 3) exclusive scan per slice (4096 bins). 32 CTAs x 256 thr, 16 bins/thread.
// ---------------------------------------------------------------------------
__global__ void k_scan() {
    const int slice = blockIdx.x;
    const int tid = threadIdx.x;
    const int* cnt = g_cnt + slice * NBINS;
    int* start = g_start + slice * (NBINS + 1);
    int* cur   = g_cursor + slice * NBINS;

    int loc[16]; int run = 0;
    #pragma unroll
    for (int i = 0; i < 16; i++) { loc[i] = run; run += cnt[tid * 16 + i]; }

    __shared__ int stot[256];
    stot[tid] = run;
    __syncthreads();
    for (int off = 1; off < 256; off <<= 1) {
        int v = (tid >= off) ? stot[tid - off] : 0;
        __syncthreads();
        stot[tid] += v;
        __syncthreads();
    }
    int base = (tid == 0) ? 0 : stot[tid - 1];
    #pragma unroll
    for (int i = 0; i < 16; i++) {
        int v = base + loc[i];
        start[tid * 16 + i] = v;
        cur[tid * 16 + i] = v;
    }
    if (tid == 255) start[NBINS] = stot[255];
}

// ---------------------------------------------------------------------------
// 4) scatter into sorted order (order within bin arbitrary; min is invariant)
// ---------------------------------------------------------------------------
__global__ void k_scatter(const float* __restrict__ pt1, const float* __restrict__ pt2) {
    const int i = blockIdx.x * 256 + threadIdx.x;
    const int n = blockIdx.y, s = blockIdx.z;
    const int slice = n * 2 + s;
    float2 p = reinterpret_cast<const float2*>(s ? pt2 : pt1)[n * P + i];
    if (in_box(p)) {
        int b = bin_coord(p.y) * G + bin_coord(p.x);
        int pos = atomicAdd(&g_cursor[slice * NBINS + b], 1);
        g_spts[slice * P + pos] = p;
    } else {
        int pos = atomicAdd(&g_ovfcnt[slice], 1);
        g_ovf[slice * P + pos] = p;
    }
}

// ---------------------------------------------------------------------------
// 5) exact NN via expanding ring search. grid (16, NOBJ, 2); 256 threads.
//    qs = blockIdx.z selects query set; refs = other set. Queries processed
//    in SORTED order (warp-coherent rings). Overflow refs scanned by all.
// ---------------------------------------------------------------------------
__global__ void k_nn() {
    const int n = blockIdx.y, qs = blockIdx.z, rs = 1 - qs;
    const int tid = threadIdx.x;
    const int qslice = n * 2 + qs, rslice = n * 2 + rs;
    const int i = blockIdx.x * 256 + tid;

    const int nb_q = g_start[qslice * (NBINS + 1) + NBINS];
    float2 qpt = (i < nb_q) ? g_spts[qslice * P + i]
                            : g_ovf[qslice * P + (i - nb_q)];
    const int* rstart = g_start + rslice * (NBINS + 1);
    const float2* rp = g_spts + rslice * P;

    const float qx = qpt.x, qy = qpt.y;
    const int bx = bin_coord(qx), by = bin_coord(qy);
    float best = FLT_MAX;

    #define SCANBIN(bi, bj) do {                                   \
        int _b = (bj) * G + (bi);                                  \
        int _e = rstart[_b + 1];                                   \
        for (int _t = rstart[_b]; _t < _e; _t++) {                 \
            float2 _p = rp[_t];                                    \
            float _dx = qx - _p.x, _dy = qy - _p.y;                \
            best = fminf(best, fmaf(_dx, _dx, _dy * _dy));         \
        }                                                          \
    } while (0)

    for (int k = 0; k < G; k++) {
        if (k == 0) {
            SCANBIN(bx, by);
        } else {
            const int ilo = bx - k, ihi = bx + k;
            const int jlo = by - k, jhi = by + k;
            const int i0 = max(ilo, 0), i1 = min(ihi, G - 1);
            for (int ii = i0; ii <= i1; ii++) {
                if (jlo >= 0) SCANBIN(ii, jlo);
                if (jhi < G)  SCANBIN(ii, jhi);
            }
            const int j0 = max(jlo + 1, 0), j1 = min(jhi - 1, G - 1);
            for (int jj = j0; jj <= j1; jj++) {
                if (ilo >= 0) SCANBIN(ilo, jj);
                if (ihi < G)  SCANBIN(ihi, jj);
            }
        }
        // scanned region R = [bx-k, bx+k] x [by-k, by+k] in bin space.
        // all unscanned binned refs lie outside R in coord space.
        float xlo = GLO + (bx - k) * CELL, xhi = GLO + (bx + k + 1) * CELL;
        float ylo = GLO + (by - k) * CELL, yhi = GLO + (by + k + 1) * CELL;
        float lb = fminf(fminf(qx - xlo, xhi - qx), fminf(qy - ylo, yhi - qy));
        if (lb > 0.0f && lb * lb >= best) break;
    }

    // overflow refs (expected 0, correctness regardless)
    const int no_r = P - rstart[NBINS];
    const float2* rovf = g_ovf + rslice * P;
    for (int t = 0; t < no_r; t++) {
        float2 p = rovf[t];
        float dx = qx - p.x, dy = qy - p.y;
        best = fminf(best, fmaf(dx, dx, dy * dy));
    }

    float d = sqrtf(fmaxf(best, EPSF));

    __shared__ float sred[256];
    sred[tid] = d;
    __syncthreads();
    #pragma unroll
    for (int st = 128; st > 0; st >>= 1) {
        if (tid < st) sred[tid] += sred[tid + st];
        __syncthreads();
    }
    if (tid == 0) g_sum[(qs * NOBJ + n) * 16 + blockIdx.x] = sred[0];
}

// ---------------------------------------------------------------------------
// 6) finalize stage 1: one block per object (mask + masked cost)
// ---------------------------------------------------------------------------
__global__ void k_final1(const float* __restrict__ pt2) {
    __shared__ float sred[256];
    const int n = blockIdx.x, tid = threadIdx.x;

    float s = 0.0f;
    const float4* p = reinterpret_cast<const float4*>(pt2 + n * P * 2);
    #pragma unroll
    for (int i = 0; i < (P * 2 / 4) / 256; i++) {
        float4 v = p[i * 256 + tid];
        s += (v.x + v.y) + (v.z + v.w);
    }
    sred[tid] = s;
    __syncthreads();
    #pragma unroll
    for (int st = 128; st > 0; st >>= 1) {
        if (tid < st) sred[tid] += sred[tid + st];
        __syncthreads();
    }
    if (tid == 0) {
        float mask = sred[0];
        float s1 = 0.0f, s2 = 0.0f;
        #pragma unroll
        for (int t = 0; t < 16; t++) {
            s1 += g_sum[(0 * NOBJ + n) * 16 + t];   // queries = set1 (d1)
            s2 += g_sum[(1 * NOBJ + n) * 16 + t];   // queries = set2 (d2)
        }
        g_cost[n] = (mask >= 0.0f) ? 0.5f * (s1 + s2) * (1.0f / P) : 0.0f;
    }
}

// 7) finalize stage 2
__global__ void k_final2(float* __restrict__ out) {
    if (threadIdx.x == 0) {
        float s = 0.0f;
        #pragma unroll
        for (int t = 0; t < NOBJ; t++) s += g_cost[t];
        out[0] = s * (1.0f / NOBJ);
    }
}

// ---------------------------------------------------------------------------
extern "C" void kernel_launch(void* const* d_in, const int* in_sizes, int n_in,
                              void* d_out, int out_size) {
    const float* pt1 = reinterpret_cast<const float*>(d_in[0]);
    const float* pt2 = reinterpret_cast<const float*>(d_in[1]);
    float* out = reinterpret_cast<float*>(d_out);
    (void)in_sizes; (void)n_in; (void)out_size;

    dim3 gpts(P / 256, NOBJ, 2);
    k_zero   <<<(NOBJ * 2 * NBINS + 255) / 256, 256>>>();
    k_count  <<<gpts, 256>>>(pt1, pt2);
    k_scan   <<<NOBJ * 2, 256>>>();
    k_scatter<<<gpts, 256>>>(pt1, pt2);
    k_nn     <<<dim3(P / 256, NOBJ, 2), 256>>>();
    k_final1 <<<NOBJ, 256>>>(pt2);
    k_final2 <<<1, 32>>>(out);
}